// round 1
// baseline (speedup 1.0000x reference)
#include <cuda_runtime.h>

#define N_PTS 16384
#define HID   256
#define RT    16        // rows per MLP block
#define TILE  1024      // column tile for distance kernel

__device__ float g_gen[N_PTS * 2];

__device__ __forceinline__ float fsqrt_fast(float x){ float r; asm("sqrt.approx.f32 %0, %1;" : "=f"(r) : "f"(x)); return r; }
__device__ __forceinline__ float fexp2_fast(float x){ float r; asm("ex2.approx.f32 %0, %1;"  : "=f"(r) : "f"(x)); return r; }
__device__ __forceinline__ float flog2_fast(float x){ float r; asm("lg2.approx.f32 %0, %1;"  : "=f"(r) : "f"(x)); return r; }

__device__ __forceinline__ float selu_f(float x){
    const float L  = 1.0507009873554805f;
    const float LA = 1.7580993408473766f;   // L * alpha
    float e   = fexp2_fast(x * 1.4426950408889634f);
    float neg = LA * (e - 1.0f);
    return x > 0.0f ? L * x : neg;
}

// One layer: in_sh [RT][260] (row-major, padded), W [IN][256], each thread owns
// output neuron t and accumulates RT rows. Broadcast LDS.128 on activations.
template<int IN>
__device__ __forceinline__ void mlp_layer(const float (*in_sh)[260], float (*out_sh)[260],
                                          const float* __restrict__ W,
                                          const float* __restrict__ B, int t)
{
    float acc[RT];
    float bv = B[t];
    #pragma unroll
    for (int r = 0; r < RT; r++) acc[r] = bv;

    #pragma unroll 1
    for (int k = 0; k < IN; k += 8){
        float w0 = W[(k+0)*HID + t]; float w1 = W[(k+1)*HID + t];
        float w2 = W[(k+2)*HID + t]; float w3 = W[(k+3)*HID + t];
        float w4 = W[(k+4)*HID + t]; float w5 = W[(k+5)*HID + t];
        float w6 = W[(k+6)*HID + t]; float w7 = W[(k+7)*HID + t];
        #pragma unroll
        for (int r = 0; r < RT; r++){
            float4 h0 = *reinterpret_cast<const float4*>(&in_sh[r][k]);
            float4 h1 = *reinterpret_cast<const float4*>(&in_sh[r][k+4]);
            float a = acc[r];
            a = fmaf(h0.x, w0, a); a = fmaf(h0.y, w1, a);
            a = fmaf(h0.z, w2, a); a = fmaf(h0.w, w3, a);
            a = fmaf(h1.x, w4, a); a = fmaf(h1.y, w5, a);
            a = fmaf(h1.z, w6, a); a = fmaf(h1.w, w7, a);
            acc[r] = a;
        }
    }
    #pragma unroll
    for (int r = 0; r < RT; r++) out_sh[r][t] = selu_f(acc[r]);
}

__global__ __launch_bounds__(256) void mlp_kernel(
    const float* __restrict__ z,
    const float* __restrict__ W1, const float* __restrict__ b1,
    const float* __restrict__ W2, const float* __restrict__ b2,
    const float* __restrict__ W3, const float* __restrict__ b3,
    const float* __restrict__ W4, const float* __restrict__ b4,
    const float* __restrict__ W5, const float* __restrict__ b5)
{
    __shared__ float ha[RT][260];
    __shared__ float hb[RT][260];
    int t    = threadIdx.x;
    int row0 = blockIdx.x * RT;

    // stage z tile: ha[r][k], k < 32
    for (int e = t; e < RT * 32; e += 256) ha[e >> 5][e & 31] = z[row0 * 32 + e];
    __syncthreads();

    mlp_layer<32 >(ha, hb, W1, b1, t);  __syncthreads();
    mlp_layer<256>(hb, ha, W2, b2, t);  __syncthreads();
    mlp_layer<256>(ha, hb, W3, b3, t);  __syncthreads();
    mlp_layer<256>(hb, ha, W4, b4, t);  __syncthreads();

    // final 256 -> 2 projection: 32 threads, one (row, dim) each
    if (t < 32){
        int r = t >> 1, d = t & 1;
        float s = b5[d];
        #pragma unroll 4
        for (int k = 0; k < HID; k++) s = fmaf(ha[r][k], W5[k*2 + d], s);
        g_gen[(row0 + r) * 2 + d] = s;
    }
}

// One warp per row. Pass A: exact row minima of squared distances (no MUFU).
// Pass B: base-2 logsumexp with the pass-A max folded in analytically.
__global__ __launch_bounds__(256) void energy_kernel(const float* __restrict__ pos,
                                                     float* __restrict__ out)
{
    __shared__ float2 sp[TILE];
    __shared__ float2 sg[TILE];
    const float K    = 28.853900817779268f;   // 1/(TEMP*ln2)
    const float TLN2 = 0.034657359027997264f; // TEMP*ln2

    int lane = threadIdx.x & 31;
    int w    = threadIdx.x >> 5;
    int row  = blockIdx.x * 8 + w;

    float gx = g_gen[row*2], gy = g_gen[row*2 + 1];
    const float2* posv = reinterpret_cast<const float2*>(pos);
    const float2* genv = reinterpret_cast<const float2*>(g_gen);

    // ---- pass A: min squared distances ----
    float mp = 3.0e38f, mn = 3.0e38f;
    for (int tb = 0; tb < N_PTS; tb += TILE){
        __syncthreads();
        for (int e = threadIdx.x; e < TILE; e += 256){ sp[e] = posv[tb+e]; sg[e] = genv[tb+e]; }
        __syncthreads();
        int jr = row - tb;
        #pragma unroll 4
        for (int j = lane; j < TILE; j += 32){
            float2 p = sp[j];
            float dx = gx - p.x, dy = gy - p.y;
            float d2 = fmaf(dy, dy, dx*dx);
            mp = fminf(mp, d2);
            float2 q = sg[j];
            float ex_ = gx - q.x, ey = gy - q.y;
            float e2  = fmaf(ey, ey, ex_*ex_);
            if (j != jr) mn = fminf(mn, e2);
        }
    }
    #pragma unroll
    for (int o = 16; o; o >>= 1){
        mp = fminf(mp, __shfl_xor_sync(0xffffffffu, mp, o));
        mn = fminf(mn, __shfl_xor_sync(0xffffffffu, mn, o));
    }
    float dminp = fsqrt_fast(mp);
    float dminn = fsqrt_fast(mn);
    float Mp = K * dminp, Mn = K * dminn;

    // ---- pass B: sums of exp2(-K*d + M) ----
    float sps = 0.0f, sns = 0.0f;
    for (int tb = 0; tb < N_PTS; tb += TILE){
        __syncthreads();
        for (int e = threadIdx.x; e < TILE; e += 256){ sp[e] = posv[tb+e]; sg[e] = genv[tb+e]; }
        __syncthreads();
        int jr = row - tb;
        #pragma unroll 4
        for (int j = lane; j < TILE; j += 32){
            float2 p = sp[j];
            float dx = gx - p.x, dy = gy - p.y;
            float d2 = fmaf(dy, dy, dx*dx);
            float d  = fsqrt_fast(d2);
            sps += fexp2_fast(fmaf(d, -K, Mp));
            float2 q = sg[j];
            float ex_ = gx - q.x, ey = gy - q.y;
            float e2  = fmaf(ey, ey, ex_*ex_);
            float dn  = fsqrt_fast(e2);
            float en  = fexp2_fast(fmaf(dn, -K, Mn));
            sns += (j == jr) ? 0.0f : en;
        }
    }
    #pragma unroll
    for (int o = 16; o; o >>= 1){
        sps += __shfl_xor_sync(0xffffffffu, sps, o);
        sns += __shfl_xor_sync(0xffffffffu, sns, o);
    }

    if (lane == 0)
        out[row] = (dminp - dminn) + TLN2 * (flog2_fast(sns) - flog2_fast(sps));
}

extern "C" void kernel_launch(void* const* d_in, const int* in_sizes, int n_in,
                              void* d_out, int out_size)
{
    const float* pos = (const float*)d_in[0];
    const float* z   = (const float*)d_in[1];
    const float* W1  = (const float*)d_in[2];  const float* b1 = (const float*)d_in[3];
    const float* W2  = (const float*)d_in[4];  const float* b2 = (const float*)d_in[5];
    const float* W3  = (const float*)d_in[6];  const float* b3 = (const float*)d_in[7];
    const float* W4  = (const float*)d_in[8];  const float* b4 = (const float*)d_in[9];
    const float* W5  = (const float*)d_in[10]; const float* b5 = (const float*)d_in[11];
    (void)in_sizes; (void)n_in; (void)out_size;

    mlp_kernel<<<N_PTS / RT, 256>>>(z, W1, b1, W2, b2, W3, b3, W4, b4, W5, b5);
    energy_kernel<<<N_PTS / 8, 256>>>(pos, (float*)d_out);
}

// round 5
// speedup vs baseline: 1.0763x; 1.0763x over previous
#include <cuda_runtime.h>

#define N_PTS 16384
#define HID   256
#define RT    16        // rows per MLP block
#define TILE  1024      // column tile for distance kernel

typedef unsigned long long ull;

__device__ float g_gen[N_PTS * 2];

__device__ __forceinline__ float fsqrt_fast(float x){ float r; asm("sqrt.approx.f32 %0, %1;" : "=f"(r) : "f"(x)); return r; }
__device__ __forceinline__ float fexp2_fast(float x){ float r; asm("ex2.approx.f32 %0, %1;"  : "=f"(r) : "f"(x)); return r; }
__device__ __forceinline__ float flog2_fast(float x){ float r; asm("lg2.approx.f32 %0, %1;"  : "=f"(r) : "f"(x)); return r; }

__device__ __forceinline__ ull f2ull(float a, float b){
    ull v; asm("mov.b64 %0, {%1, %2};" : "=l"(v) : "f"(a), "f"(b)); return v;
}
__device__ __forceinline__ void ull2f2(ull v, float& a, float& b){
    asm("mov.b64 {%0, %1}, %2;" : "=f"(a), "=f"(b) : "l"(v));
}

__device__ __forceinline__ float selu_f(float x){
    const float L  = 1.0507009873554805f;
    const float LA = 1.7580993408473766f;   // L * alpha
    float e   = fexp2_fast(x * 1.4426950408889634f);
    float neg = LA * (e - 1.0f);
    return x > 0.0f ? L * x : neg;
}

// One layer with packed f32x2 FMAs over the k dimension.
// in_sh [RT][260] row-major; thread t owns output neuron t for all RT rows.
// acc is a raw .b64 pair {even-k partial, odd-k partial}; horizontal add at end.
template<int IN>
__device__ __forceinline__ void mlp_layer(const float (*in_sh)[260], float (*out_sh)[260],
                                          const float* __restrict__ W,
                                          const float* __restrict__ B, int t)
{
    ull acc[RT];
    float bv = B[t];
    #pragma unroll
    for (int r = 0; r < RT; r++) acc[r] = f2ull(bv, 0.0f);

    #pragma unroll 1
    for (int k = 0; k < IN; k += 4){
        const float* Wk = W + k * HID + t;
        float w0 = Wk[0];
        float w1 = Wk[HID];
        float w2 = Wk[2 * HID];
        float w3 = Wk[3 * HID];
        ull wp0 = f2ull(w0, w1);
        ull wp1 = f2ull(w2, w3);
        #pragma unroll
        for (int r = 0; r < RT; r++){
            ulonglong2 hv = *reinterpret_cast<const ulonglong2*>(&in_sh[r][k]);
            asm("fma.rn.f32x2 %0, %1, %2, %0;" : "+l"(acc[r]) : "l"(hv.x), "l"(wp0));
            asm("fma.rn.f32x2 %0, %1, %2, %0;" : "+l"(acc[r]) : "l"(hv.y), "l"(wp1));
        }
    }
    #pragma unroll
    for (int r = 0; r < RT; r++){
        float lo, hi; ull2f2(acc[r], lo, hi);
        out_sh[r][t] = selu_f(lo + hi);
    }
}

__global__ __launch_bounds__(256) void mlp_kernel(
    const float* __restrict__ z,
    const float* __restrict__ W1, const float* __restrict__ b1,
    const float* __restrict__ W2, const float* __restrict__ b2,
    const float* __restrict__ W3, const float* __restrict__ b3,
    const float* __restrict__ W4, const float* __restrict__ b4,
    const float* __restrict__ W5, const float* __restrict__ b5)
{
    __shared__ float ha[RT][260];
    __shared__ float hb[RT][260];
    int t    = threadIdx.x;
    int row0 = blockIdx.x * RT;

    // stage z tile: ha[r][k], k < 32
    for (int e = t; e < RT * 32; e += 256) ha[e >> 5][e & 31] = z[row0 * 32 + e];
    __syncthreads();

    mlp_layer<32 >(ha, hb, W1, b1, t);  __syncthreads();
    mlp_layer<256>(hb, ha, W2, b2, t);  __syncthreads();
    mlp_layer<256>(ha, hb, W3, b3, t);  __syncthreads();
    mlp_layer<256>(hb, ha, W4, b4, t);  __syncthreads();
    // layer-4 output lives in ha

    // final 256 -> 2 projection: 32 threads, one (row, dim) each
    if (t < 32){
        int r = t >> 1, d = t & 1;
        float s = b5[d];
        #pragma unroll 4
        for (int k = 0; k < HID; k++) s = fmaf(ha[r][k], W5[k*2 + d], s);
        g_gen[(row0 + r) * 2 + d] = s;
    }
}

// One warp per row, single pass. Fixed bias M=64 inside exp2 keeps every
// relevant term representable; the bias cancels exactly in the pos/neg
// log ratio, so no min/max pre-pass is needed.
__global__ __launch_bounds__(256) void energy_kernel(const float* __restrict__ pos,
                                                     float* __restrict__ out)
{
    __shared__ float2 sp[TILE];
    __shared__ float2 sg[TILE];
    const float K    = 28.853900817779268f;   // 1/(TEMP*ln2)
    const float TLN2 = 0.034657359027997264f; // TEMP*ln2
    const float BIAS = 64.0f;

    int lane = threadIdx.x & 31;
    int w    = threadIdx.x >> 5;
    int row  = blockIdx.x * 8 + w;

    float gx = g_gen[row*2], gy = g_gen[row*2 + 1];
    const float2* posv = reinterpret_cast<const float2*>(pos);
    const float2* genv = reinterpret_cast<const float2*>(g_gen);

    float sps = 0.0f, sns = 0.0f;
    for (int tb = 0; tb < N_PTS; tb += TILE){
        __syncthreads();
        for (int e = threadIdx.x; e < TILE; e += 256){ sp[e] = posv[tb+e]; sg[e] = genv[tb+e]; }
        __syncthreads();
        int jr = row - tb;
        #pragma unroll 4
        for (int j = lane; j < TILE; j += 32){
            float2 p = sp[j];
            float dx = gx - p.x, dy = gy - p.y;
            float d2 = fmaf(dy, dy, dx*dx);
            float d  = fsqrt_fast(d2);
            sps += fexp2_fast(fmaf(d, -K, BIAS));

            float2 q = sg[j];
            float ex_ = gx - q.x, ey = gy - q.y;
            float e2  = fmaf(ey, ey, ex_*ex_);
            float dn  = fsqrt_fast(e2);
            float en  = fexp2_fast(fmaf(dn, -K, BIAS));
            sns += (j == jr) ? 0.0f : en;
        }
    }
    #pragma unroll
    for (int o = 16; o; o >>= 1){
        sps += __shfl_xor_sync(0xffffffffu, sps, o);
        sns += __shfl_xor_sync(0xffffffffu, sns, o);
    }

    if (lane == 0)
        out[row] = TLN2 * (flog2_fast(sns) - flog2_fast(sps));
}

extern "C" void kernel_launch(void* const* d_in, const int* in_sizes, int n_in,
                              void* d_out, int out_size)
{
    const float* pos = (const float*)d_in[0];
    const float* z   = (const float*)d_in[1];
    const float* W1  = (const float*)d_in[2];  const float* b1 = (const float*)d_in[3];
    const float* W2  = (const float*)d_in[4];  const float* b2 = (const float*)d_in[5];
    const float* W3  = (const float*)d_in[6];  const float* b3 = (const float*)d_in[7];
    const float* W4  = (const float*)d_in[8];  const float* b4 = (const float*)d_in[9];
    const float* W5  = (const float*)d_in[10]; const float* b5 = (const float*)d_in[11];
    (void)in_sizes; (void)n_in; (void)out_size;

    mlp_kernel<<<N_PTS / RT, 256>>>(z, W1, b1, W2, b2, W3, b3, W4, b4, W5, b5);
    energy_kernel<<<N_PTS / 8, 256>>>(pos, (float*)d_out);
}

// round 7
// speedup vs baseline: 1.4977x; 1.3916x over previous
#include <cuda_runtime.h>

#define N_PTS 16384
#define HID   256
#define RT    16        // rows per MLP block
#define TILE  1024      // column tile for distance kernel

typedef unsigned long long ull;

__device__ float g_gen[N_PTS * 2];

__device__ __forceinline__ float fsqrt_fast(float x){ float r; asm("sqrt.approx.f32 %0, %1;" : "=f"(r) : "f"(x)); return r; }
__device__ __forceinline__ float fexp2_fast(float x){ float r; asm("ex2.approx.f32 %0, %1;"  : "=f"(r) : "f"(x)); return r; }
__device__ __forceinline__ float flog2_fast(float x){ float r; asm("lg2.approx.f32 %0, %1;"  : "=f"(r) : "f"(x)); return r; }

__device__ __forceinline__ ull pack2(float a, float b){
    ull v; asm("mov.b64 %0, {%1, %2};" : "=l"(v) : "f"(a), "f"(b)); return v;
}
__device__ __forceinline__ void unpack2(ull v, float& a, float& b){
    asm("mov.b64 {%0, %1}, %2;" : "=f"(a), "=f"(b) : "l"(v));
}
__device__ __forceinline__ ull add2(ull a, ull b){
    ull r; asm("add.rn.f32x2 %0, %1, %2;" : "=l"(r) : "l"(a), "l"(b)); return r;
}
__device__ __forceinline__ ull mul2(ull a, ull b){
    ull r; asm("mul.rn.f32x2 %0, %1, %2;" : "=l"(r) : "l"(a), "l"(b)); return r;
}
__device__ __forceinline__ ull fma2(ull a, ull b, ull c){
    ull r; asm("fma.rn.f32x2 %0, %1, %2, %3;" : "=l"(r) : "l"(a), "l"(b), "l"(c)); return r;
}

__device__ __forceinline__ float selu_f(float x){
    const float L  = 1.0507009873554805f;
    const float LA = 1.7580993408473766f;   // L * alpha
    float e   = fexp2_fast(x * 1.4426950408889634f);
    float neg = LA * (e - 1.0f);
    return x > 0.0f ? L * x : neg;
}

// ---------------- MLP ----------------
// 128 threads/block; thread t owns output neurons t and t+128 for RT rows.
// Scalar FFMA (proven fast); each LDS.128 of activations feeds 16 FFMAs.
template<int IN>
__device__ __forceinline__ void mlp_layer(const float (*in_sh)[260], float (*out_sh)[260],
                                          const float* __restrict__ W,
                                          const float* __restrict__ B, int t)
{
    float acca[RT], accb[RT];
    float bva = B[t], bvb = B[t + 128];
    #pragma unroll
    for (int r = 0; r < RT; r++){ acca[r] = bva; accb[r] = bvb; }

    #pragma unroll 1
    for (int k = 0; k < IN; k += 8){
        const float* Wk = W + k * HID + t;
        float wa[8], wb[8];
        #pragma unroll
        for (int i = 0; i < 8; i++){ wa[i] = Wk[i * HID]; wb[i] = Wk[i * HID + 128]; }
        #pragma unroll
        for (int r = 0; r < RT; r++){
            float4 h0 = *reinterpret_cast<const float4*>(&in_sh[r][k]);
            float4 h1 = *reinterpret_cast<const float4*>(&in_sh[r][k+4]);
            float a = acca[r], b = accb[r];
            a = fmaf(h0.x, wa[0], a); b = fmaf(h0.x, wb[0], b);
            a = fmaf(h0.y, wa[1], a); b = fmaf(h0.y, wb[1], b);
            a = fmaf(h0.z, wa[2], a); b = fmaf(h0.z, wb[2], b);
            a = fmaf(h0.w, wa[3], a); b = fmaf(h0.w, wb[3], b);
            a = fmaf(h1.x, wa[4], a); b = fmaf(h1.x, wb[4], b);
            a = fmaf(h1.y, wa[5], a); b = fmaf(h1.y, wb[5], b);
            a = fmaf(h1.z, wa[6], a); b = fmaf(h1.z, wb[6], b);
            a = fmaf(h1.w, wa[7], a); b = fmaf(h1.w, wb[7], b);
            acca[r] = a; accb[r] = b;
        }
    }
    #pragma unroll
    for (int r = 0; r < RT; r++){
        out_sh[r][t]       = selu_f(acca[r]);
        out_sh[r][t + 128] = selu_f(accb[r]);
    }
}

__global__ __launch_bounds__(128) void mlp_kernel(
    const float* __restrict__ z,
    const float* __restrict__ W1, const float* __restrict__ b1,
    const float* __restrict__ W2, const float* __restrict__ b2,
    const float* __restrict__ W3, const float* __restrict__ b3,
    const float* __restrict__ W4, const float* __restrict__ b4,
    const float* __restrict__ W5, const float* __restrict__ b5)
{
    __shared__ float ha[RT][260];
    __shared__ float hb[RT][260];
    int t    = threadIdx.x;
    int row0 = blockIdx.x * RT;

    // stage z tile: ha[r][k], k < 32
    for (int e = t; e < RT * 32; e += 128) ha[e >> 5][e & 31] = z[row0 * 32 + e];
    __syncthreads();

    mlp_layer<32 >(ha, hb, W1, b1, t);  __syncthreads();
    mlp_layer<256>(hb, ha, W2, b2, t);  __syncthreads();
    mlp_layer<256>(ha, hb, W3, b3, t);  __syncthreads();
    mlp_layer<256>(hb, ha, W4, b4, t);  __syncthreads();
    // layer-4 output lives in ha

    // final 256 -> 2 projection: 32 threads, one (row, dim) each
    if (t < 32){
        int r = t >> 1, d = t & 1;
        float s = b5[d];
        #pragma unroll 4
        for (int k = 0; k < HID; k++) s = fmaf(ha[r][k], W5[k*2 + d], s);
        g_gen[(row0 + r) * 2 + d] = s;
    }
}

// ---------------- Energy ----------------
// One warp per row, single pass, SoA tiles, packed f32x2 distance math,
// diagonal guard only in the single tile that contains the row's own index.
// Fixed bias 64 inside exp2 cancels exactly in the pos/neg log ratio.

struct TilePtr { const float *px, *py, *gx, *gy; };

template<bool GUARD>
__device__ __forceinline__ void accum_tile(
    const float* __restrict__ spx, const float* __restrict__ spy,
    const float* __restrict__ sgx, const float* __restrict__ sgy,
    int lane, int jr, ull ngx2, ull ngy2,
    float& sps, float& sns)
{
    const float K    = 28.853900817779268f;
    const float BIAS = 64.0f;
    #pragma unroll 4
    for (int j = lane * 2; j < TILE; j += 64){
        // positive pair (vs data points)
        {
            ull px = *reinterpret_cast<const ull*>(&spx[j]);
            ull py = *reinterpret_cast<const ull*>(&spy[j]);
            ull dx = add2(px, ngx2);
            ull dy = add2(py, ngy2);
            ull d2 = fma2(dy, dy, mul2(dx, dx));
            float a0, a1; unpack2(d2, a0, a1);
            float d0 = fsqrt_fast(a0), d1 = fsqrt_fast(a1);
            sps += fexp2_fast(fmaf(d0, -K, BIAS));
            sps += fexp2_fast(fmaf(d1, -K, BIAS));
        }
        // negative pair (vs generated points)
        {
            ull qx = *reinterpret_cast<const ull*>(&sgx[j]);
            ull qy = *reinterpret_cast<const ull*>(&sgy[j]);
            ull dx = add2(qx, ngx2);
            ull dy = add2(qy, ngy2);
            ull d2 = fma2(dy, dy, mul2(dx, dx));
            float a0, a1; unpack2(d2, a0, a1);
            float d0 = fsqrt_fast(a0), d1 = fsqrt_fast(a1);
            float e0 = fexp2_fast(fmaf(d0, -K, BIAS));
            float e1 = fexp2_fast(fmaf(d1, -K, BIAS));
            if (GUARD){
                if (j     == jr) e0 = 0.0f;
                if (j + 1 == jr) e1 = 0.0f;
            }
            sns += e0; sns += e1;
        }
    }
}

__global__ __launch_bounds__(256) void energy_kernel(const float* __restrict__ pos,
                                                     float* __restrict__ out)
{
    __shared__ float spx[TILE], spy[TILE], sgx[TILE], sgy[TILE];
    const float TLN2 = 0.034657359027997264f; // TEMP*ln2

    int lane = threadIdx.x & 31;
    int w    = threadIdx.x >> 5;
    int row  = blockIdx.x * 8 + w;

    float gx = g_gen[row*2], gy = g_gen[row*2 + 1];
    ull ngx2 = pack2(-gx, -gx);
    ull ngy2 = pack2(-gy, -gy);
    const float2* posv = reinterpret_cast<const float2*>(pos);
    const float2* genv = reinterpret_cast<const float2*>(g_gen);

    float sps = 0.0f, sns = 0.0f;
    for (int tb = 0; tb < N_PTS; tb += TILE){
        __syncthreads();
        for (int e = threadIdx.x; e < TILE; e += 256){
            float2 p = posv[tb + e]; spx[e] = p.x; spy[e] = p.y;
            float2 q = genv[tb + e]; sgx[e] = q.x; sgy[e] = q.y;
        }
        __syncthreads();
        int jr = row - tb;
        if (jr >= 0 && jr < TILE)
            accum_tile<true >(spx, spy, sgx, sgy, lane, jr, ngx2, ngy2, sps, sns);
        else
            accum_tile<false>(spx, spy, sgx, sgy, lane, jr, ngx2, ngy2, sps, sns);
    }
    #pragma unroll
    for (int o = 16; o; o >>= 1){
        sps += __shfl_xor_sync(0xffffffffu, sps, o);
        sns += __shfl_xor_sync(0xffffffffu, sns, o);
    }

    if (lane == 0)
        out[row] = TLN2 * (flog2_fast(sns) - flog2_fast(sps));
}

extern "C" void kernel_launch(void* const* d_in, const int* in_sizes, int n_in,
                              void* d_out, int out_size)
{
    const float* pos = (const float*)d_in[0];
    const float* z   = (const float*)d_in[1];
    const float* W1  = (const float*)d_in[2];  const float* b1 = (const float*)d_in[3];
    const float* W2  = (const float*)d_in[4];  const float* b2 = (const float*)d_in[5];
    const float* W3  = (const float*)d_in[6];  const float* b3 = (const float*)d_in[7];
    const float* W4  = (const float*)d_in[8];  const float* b4 = (const float*)d_in[9];
    const float* W5  = (const float*)d_in[10]; const float* b5 = (const float*)d_in[11];
    (void)in_sizes; (void)n_in; (void)out_size;

    mlp_kernel<<<N_PTS / RT, 128>>>(z, W1, b1, W2, b2, W3, b3, W4, b4, W5, b5);
    energy_kernel<<<N_PTS / 8, 256>>>(pos, (float*)d_out);
}

// round 8
// speedup vs baseline: 1.5334x; 1.0238x over previous
#include <cuda_runtime.h>

#define N_PTS 16384
#define HID   256
#define RT    16        // rows per MLP block
#define TILE  1024      // column tile for pos kernel
#define SB    512       // symmetry block size
#define NB    (N_PTS/SB) // 32

__device__ float g_gen[N_PTS * 2];
__device__ float g_spos[N_PTS];
__device__ float g_pneg[NB][N_PTS];   // partial neg sums: [colBlockOfOrigin][row]

__device__ __forceinline__ float fsqrt_fast(float x){ float r; asm("sqrt.approx.f32 %0, %1;" : "=f"(r) : "f"(x)); return r; }
__device__ __forceinline__ float fexp2_fast(float x){ float r; asm("ex2.approx.f32 %0, %1;"  : "=f"(r) : "f"(x)); return r; }
__device__ __forceinline__ float flog2_fast(float x){ float r; asm("lg2.approx.f32 %0, %1;"  : "=f"(r) : "f"(x)); return r; }

#define KCONST 28.853900817779268f    // 1/(TEMP*ln2)
#define TLN2C  0.034657359027997264f  // TEMP*ln2
#define BIASC  64.0f

__device__ __forceinline__ float selu_f(float x){
    const float L  = 1.0507009873554805f;
    const float LA = 1.7580993408473766f;   // L * alpha
    float e   = fexp2_fast(x * 1.4426950408889634f);
    float neg = LA * (e - 1.0f);
    return x > 0.0f ? L * x : neg;
}

// ---------------- MLP ----------------
// 128 threads/block; thread t owns output neurons t and t+128 for RT rows.
template<int IN>
__device__ __forceinline__ void mlp_layer(const float (*in_sh)[260], float (*out_sh)[260],
                                          const float* __restrict__ W,
                                          const float* __restrict__ B, int t)
{
    float acca[RT], accb[RT];
    float bva = B[t], bvb = B[t + 128];
    #pragma unroll
    for (int r = 0; r < RT; r++){ acca[r] = bva; accb[r] = bvb; }

    #pragma unroll 1
    for (int k = 0; k < IN; k += 8){
        const float* Wk = W + k * HID + t;
        float wa[8], wb[8];
        #pragma unroll
        for (int i = 0; i < 8; i++){ wa[i] = Wk[i * HID]; wb[i] = Wk[i * HID + 128]; }
        #pragma unroll
        for (int r = 0; r < RT; r++){
            float4 h0 = *reinterpret_cast<const float4*>(&in_sh[r][k]);
            float4 h1 = *reinterpret_cast<const float4*>(&in_sh[r][k+4]);
            float a = acca[r], b = accb[r];
            a = fmaf(h0.x, wa[0], a); b = fmaf(h0.x, wb[0], b);
            a = fmaf(h0.y, wa[1], a); b = fmaf(h0.y, wb[1], b);
            a = fmaf(h0.z, wa[2], a); b = fmaf(h0.z, wb[2], b);
            a = fmaf(h0.w, wa[3], a); b = fmaf(h0.w, wb[3], b);
            a = fmaf(h1.x, wa[4], a); b = fmaf(h1.x, wb[4], b);
            a = fmaf(h1.y, wa[5], a); b = fmaf(h1.y, wb[5], b);
            a = fmaf(h1.z, wa[6], a); b = fmaf(h1.z, wb[6], b);
            a = fmaf(h1.w, wa[7], a); b = fmaf(h1.w, wb[7], b);
            acca[r] = a; accb[r] = b;
        }
    }
    #pragma unroll
    for (int r = 0; r < RT; r++){
        out_sh[r][t]       = selu_f(acca[r]);
        out_sh[r][t + 128] = selu_f(accb[r]);
    }
}

__global__ __launch_bounds__(128) void mlp_kernel(
    const float* __restrict__ z,
    const float* __restrict__ W1, const float* __restrict__ b1,
    const float* __restrict__ W2, const float* __restrict__ b2,
    const float* __restrict__ W3, const float* __restrict__ b3,
    const float* __restrict__ W4, const float* __restrict__ b4,
    const float* __restrict__ W5, const float* __restrict__ b5)
{
    __shared__ float ha[RT][260];
    __shared__ float hb[RT][260];
    int t    = threadIdx.x;
    int row0 = blockIdx.x * RT;

    for (int e = t; e < RT * 32; e += 128) ha[e >> 5][e & 31] = z[row0 * 32 + e];
    __syncthreads();

    mlp_layer<32 >(ha, hb, W1, b1, t);  __syncthreads();
    mlp_layer<256>(hb, ha, W2, b2, t);  __syncthreads();
    mlp_layer<256>(ha, hb, W3, b3, t);  __syncthreads();
    mlp_layer<256>(hb, ha, W4, b4, t);  __syncthreads();
    // layer-4 output lives in ha

    if (t < 32){
        int r = t >> 1, d = t & 1;
        float s = b5[d];
        #pragma unroll 4
        for (int k = 0; k < HID; k++) s = fmaf(ha[r][k], W5[k*2 + d], s);
        g_gen[(row0 + r) * 2 + d] = s;
    }
}

// ---------------- Energy: positive side ----------------
// One warp per row over pos tiles; fixed bias 64 inside exp2 (cancels in the
// final log ratio). Writes unnormalized row sums.
__global__ __launch_bounds__(256) void pos_kernel(const float* __restrict__ pos)
{
    __shared__ float2 sp[TILE];
    int lane = threadIdx.x & 31;
    int w    = threadIdx.x >> 5;
    int row  = blockIdx.x * 8 + w;

    float gx = g_gen[row*2], gy = g_gen[row*2 + 1];
    const float2* posv = reinterpret_cast<const float2*>(pos);

    float sps = 0.0f;
    for (int tb = 0; tb < N_PTS; tb += TILE){
        __syncthreads();
        for (int e = threadIdx.x; e < TILE; e += 256) sp[e] = posv[tb + e];
        __syncthreads();
        #pragma unroll 8
        for (int j = lane; j < TILE; j += 32){
            float2 p = sp[j];
            float dx = gx - p.x, dy = gy - p.y;
            float d  = fsqrt_fast(fmaf(dy, dy, dx*dx));
            sps += fexp2_fast(fmaf(d, -KCONST, BIASC));
        }
    }
    #pragma unroll
    for (int o = 16; o; o >>= 1) sps += __shfl_xor_sync(0xffffffffu, sps, o);
    if (lane == 0) g_spos[row] = sps;
}

// ---------------- Energy: negative side (symmetric) ----------------
// Block tiles (a,b) with a<=b over 512x512 chunks of the symmetric gen-gen
// matrix. Off-diagonal tiles are computed once: each exp term feeds the row
// sum (block a rows -> g_pneg[b][...]) AND the column sum (block b rows ->
// g_pneg[a][...]). Diagonal tiles compute the full chunk with the i==j guard
// and write row sums only. Every g_pneg slot has exactly one writer.
__global__ __launch_bounds__(256) void neg_sym_kernel()
{
    int a = blockIdx.x >> 5;
    int b = blockIdx.x & 31;
    if (a > b) return;

    __shared__ float2 shr[SB];
    __shared__ float  csum_sh[8][SB];

    int tid  = threadIdx.x;
    int lane = tid & 31;
    int w    = tid >> 5;
    const float2* genv = reinterpret_cast<const float2*>(g_gen);

    // stage rows (block a)
    for (int e = tid; e < SB; e += 256) shr[e] = genv[a*SB + e];
    __syncthreads();

    // preload columns (block b) into registers: lane holds 16 points
    float cx[16], cy[16];
    #pragma unroll
    for (int cs = 0; cs < 16; cs++){
        float2 c = genv[b*SB + cs*32 + lane];
        cx[cs] = c.x; cy[cs] = c.y;
    }

    float csum[16];
    #pragma unroll
    for (int cs = 0; cs < 16; cs++) csum[cs] = 0.0f;

    bool diag = (a == b);

    #pragma unroll 1
    for (int r = 0; r < 64; r++){
        int rloc = w * 64 + r;
        float2 rp = shr[rloc];
        int rl = diag ? rloc : -1;     // local col index that equals this row
        float rs = 0.0f;
        #pragma unroll
        for (int cs = 0; cs < 16; cs++){
            float dx = rp.x - cx[cs];
            float dy = rp.y - cy[cs];
            float d  = fsqrt_fast(fmaf(dy, dy, dx*dx));
            float e  = fexp2_fast(fmaf(d, -KCONST, BIASC));
            if (cs*32 + lane == rl) e = 0.0f;
            rs += e;
            csum[cs] += e;
        }
        #pragma unroll
        for (int o = 16; o; o >>= 1) rs += __shfl_xor_sync(0xffffffffu, rs, o);
        if (lane == 0) g_pneg[b][a*SB + rloc] = rs;
    }

    if (!diag){
        #pragma unroll
        for (int cs = 0; cs < 16; cs++) csum_sh[w][cs*32 + lane] = csum[cs];
        __syncthreads();
        for (int c = tid; c < SB; c += 256){
            float s = 0.0f;
            #pragma unroll
            for (int ww = 0; ww < 8; ww++) s += csum_sh[ww][c];
            g_pneg[a][b*SB + c] = s;
        }
    }
}

// ---------------- Final reduce ----------------
__global__ __launch_bounds__(256) void reduce_kernel(float* __restrict__ out)
{
    int i = blockIdx.x * 256 + threadIdx.x;
    float sp = g_spos[i];
    float sn = 0.0f;
    #pragma unroll
    for (int k = 0; k < NB; k++) sn += g_pneg[k][i];
    out[i] = TLN2C * (flog2_fast(sn) - flog2_fast(sp));
}

extern "C" void kernel_launch(void* const* d_in, const int* in_sizes, int n_in,
                              void* d_out, int out_size)
{
    const float* pos = (const float*)d_in[0];
    const float* z   = (const float*)d_in[1];
    const float* W1  = (const float*)d_in[2];  const float* b1 = (const float*)d_in[3];
    const float* W2  = (const float*)d_in[4];  const float* b2 = (const float*)d_in[5];
    const float* W3  = (const float*)d_in[6];  const float* b3 = (const float*)d_in[7];
    const float* W4  = (const float*)d_in[8];  const float* b4 = (const float*)d_in[9];
    const float* W5  = (const float*)d_in[10]; const float* b5 = (const float*)d_in[11];
    (void)in_sizes; (void)n_in; (void)out_size;

    mlp_kernel<<<N_PTS / RT, 128>>>(z, W1, b1, W2, b2, W3, b3, W4, b4, W5, b5);
    pos_kernel<<<N_PTS / 8, 256>>>(pos);
    neg_sym_kernel<<<NB * NB, 256>>>();
    reduce_kernel<<<N_PTS / 256, 256>>>((float*)d_out);
}

// round 9
// speedup vs baseline: 1.6422x; 1.0710x over previous
#include <cuda_runtime.h>

#define N_PTS 16384
#define HID   256
#define RT    16            // rows per MLP block
#define PTILE 1024          // column tile for pos path
#define SB    256           // symmetry tile size
#define NB    (N_PTS/SB)    // 64
#define POS_BLOCKS 4096     // 2048 row-groups x 2 column halves
#define NEG_TILES  (NB*(NB+1)/2)   // 2080

__device__ float g_gen[N_PTS * 2];
__device__ float g_spos[2][N_PTS];
__device__ float g_pneg[NB][N_PTS];   // partial neg sums: [originColBlock][row]

__device__ __forceinline__ float fsqrt_fast(float x){ float r; asm("sqrt.approx.f32 %0, %1;" : "=f"(r) : "f"(x)); return r; }
__device__ __forceinline__ float fexp2_fast(float x){ float r; asm("ex2.approx.f32 %0, %1;"  : "=f"(r) : "f"(x)); return r; }
__device__ __forceinline__ float flog2_fast(float x){ float r; asm("lg2.approx.f32 %0, %1;"  : "=f"(r) : "f"(x)); return r; }

#define KCONST 28.853900817779268f    // 1/(TEMP*ln2)
#define TLN2C  0.034657359027997264f  // TEMP*ln2
#define BIASC  64.0f

__device__ __forceinline__ float selu_f(float x){
    const float L  = 1.0507009873554805f;
    const float LA = 1.7580993408473766f;   // L * alpha
    float e   = fexp2_fast(x * 1.4426950408889634f);
    float neg = LA * (e - 1.0f);
    return x > 0.0f ? L * x : neg;
}

// ---------------- MLP ----------------
template<int IN>
__device__ __forceinline__ void mlp_layer(const float (*in_sh)[260], float (*out_sh)[260],
                                          const float* __restrict__ W,
                                          const float* __restrict__ B, int t)
{
    float acca[RT], accb[RT];
    float bva = B[t], bvb = B[t + 128];
    #pragma unroll
    for (int r = 0; r < RT; r++){ acca[r] = bva; accb[r] = bvb; }

    #pragma unroll 1
    for (int k = 0; k < IN; k += 8){
        const float* Wk = W + k * HID + t;
        float wa[8], wb[8];
        #pragma unroll
        for (int i = 0; i < 8; i++){ wa[i] = Wk[i * HID]; wb[i] = Wk[i * HID + 128]; }
        #pragma unroll
        for (int r = 0; r < RT; r++){
            float4 h0 = *reinterpret_cast<const float4*>(&in_sh[r][k]);
            float4 h1 = *reinterpret_cast<const float4*>(&in_sh[r][k+4]);
            float a = acca[r], b = accb[r];
            a = fmaf(h0.x, wa[0], a); b = fmaf(h0.x, wb[0], b);
            a = fmaf(h0.y, wa[1], a); b = fmaf(h0.y, wb[1], b);
            a = fmaf(h0.z, wa[2], a); b = fmaf(h0.z, wb[2], b);
            a = fmaf(h0.w, wa[3], a); b = fmaf(h0.w, wb[3], b);
            a = fmaf(h1.x, wa[4], a); b = fmaf(h1.x, wb[4], b);
            a = fmaf(h1.y, wa[5], a); b = fmaf(h1.y, wb[5], b);
            a = fmaf(h1.z, wa[6], a); b = fmaf(h1.z, wb[6], b);
            a = fmaf(h1.w, wa[7], a); b = fmaf(h1.w, wb[7], b);
            acca[r] = a; accb[r] = b;
        }
    }
    #pragma unroll
    for (int r = 0; r < RT; r++){
        out_sh[r][t]       = selu_f(acca[r]);
        out_sh[r][t + 128] = selu_f(accb[r]);
    }
}

__global__ __launch_bounds__(128) void mlp_kernel(
    const float* __restrict__ z,
    const float* __restrict__ W1, const float* __restrict__ b1,
    const float* __restrict__ W2, const float* __restrict__ b2,
    const float* __restrict__ W3, const float* __restrict__ b3,
    const float* __restrict__ W4, const float* __restrict__ b4,
    const float* __restrict__ W5, const float* __restrict__ b5)
{
    __shared__ float ha[RT][260];
    __shared__ float hb[RT][260];
    int t    = threadIdx.x;
    int row0 = blockIdx.x * RT;

    for (int e = t; e < RT * 32; e += 128) ha[e >> 5][e & 31] = z[row0 * 32 + e];
    __syncthreads();

    mlp_layer<32 >(ha, hb, W1, b1, t);  __syncthreads();
    mlp_layer<256>(hb, ha, W2, b2, t);  __syncthreads();
    mlp_layer<256>(ha, hb, W3, b3, t);  __syncthreads();
    mlp_layer<256>(hb, ha, W4, b4, t);  __syncthreads();
    // layer-4 output lives in ha

    if (t < 32){
        int r = t >> 1, d = t & 1;
        float s = b5[d];
        #pragma unroll 4
        for (int k = 0; k < HID; k++) s = fmaf(ha[r][k], W5[k*2 + d], s);
        g_gen[(row0 + r) * 2 + d] = s;
    }
}

// ---------------- Fused energy kernel ----------------
// Blocks [0, POS_BLOCKS): pos path. Block p: rows (p>>1)*8..+7, cols half (p&1).
// Blocks [POS_BLOCKS, +NEG_TILES): neg path, triangular tile (a<=b) of 256x256
// over the symmetric gen-gen matrix; off-diag tiles credit both row and column
// sums. All block types have equal per-warp MUFU work (256 iters) for packing.
// Fixed bias 64 inside exp2 cancels exactly in the final pos/neg log ratio.
__global__ __launch_bounds__(256) void energy_kernel(const float* __restrict__ pos)
{
    __shared__ __align__(16) float smem_raw[2560];   // 10KB, aliased per path

    int tid  = threadIdx.x;
    int lane = tid & 31;
    int w    = tid >> 5;

    if (blockIdx.x < POS_BLOCKS){
        float2* sp = reinterpret_cast<float2*>(smem_raw);   // 1024 float2 = 8KB
        int rg   = blockIdx.x >> 1;
        int half = blockIdx.x & 1;
        int row  = rg * 8 + w;

        float gx = g_gen[row*2], gy = g_gen[row*2 + 1];
        const float2* posv = reinterpret_cast<const float2*>(pos);

        float sps = 0.0f;
        int base = half * (N_PTS / 2);
        for (int tb = base; tb < base + N_PTS/2; tb += PTILE){
            __syncthreads();
            for (int e = tid; e < PTILE; e += 256) sp[e] = posv[tb + e];
            __syncthreads();
            #pragma unroll 8
            for (int j = lane; j < PTILE; j += 32){
                float2 p = sp[j];
                float dx = gx - p.x, dy = gy - p.y;
                float d  = fsqrt_fast(fmaf(dy, dy, dx*dx));
                sps += fexp2_fast(fmaf(d, -KCONST, BIASC));
            }
        }
        #pragma unroll
        for (int o = 16; o; o >>= 1) sps += __shfl_xor_sync(0xffffffffu, sps, o);
        if (lane == 0) g_spos[half][row] = sps;
    } else {
        int t = blockIdx.x - POS_BLOCKS;
        // triangular decode: offset(a) = a*NB - a*(a-1)/2, b = a + t - offset(a)
        int a = (int)(((float)NB + 0.5f) - fsqrt_fast(((float)NB + 0.5f)*((float)NB + 0.5f) - 2.0f*(float)t));
        if (a > NB - 1) a = NB - 1;
        while (a > 0 && a*NB - (a*(a-1))/2 > t) a--;
        while ((a+1)*NB - ((a+1)*a)/2 <= t) a++;
        int b = a + (t - (a*NB - (a*(a-1))/2));

        float2* shr = reinterpret_cast<float2*>(smem_raw);                 // 256 float2 = 2KB
        float (*csum_sh)[SB] = reinterpret_cast<float (*)[SB]>(smem_raw + 512); // 8x256 = 8KB

        const float2* genv = reinterpret_cast<const float2*>(g_gen);

        // stage rows (block a)
        for (int e = tid; e < SB; e += 256) shr[e] = genv[a*SB + e];
        __syncthreads();

        // columns (block b) in registers: lane holds 8 points
        float cx[8], cy[8], csum[8];
        #pragma unroll
        for (int cs = 0; cs < 8; cs++){
            float2 c = genv[b*SB + cs*32 + lane];
            cx[cs] = c.x; cy[cs] = c.y; csum[cs] = 0.0f;
        }

        bool diag = (a == b);

        #pragma unroll 1
        for (int r = 0; r < 32; r++){
            int rloc = w * 32 + r;
            float2 rp = shr[rloc];
            int rl = diag ? rloc : -1;
            float rs = 0.0f;
            #pragma unroll
            for (int cs = 0; cs < 8; cs++){
                float dx = rp.x - cx[cs];
                float dy = rp.y - cy[cs];
                float d  = fsqrt_fast(fmaf(dy, dy, dx*dx));
                float e  = fexp2_fast(fmaf(d, -KCONST, BIASC));
                if (cs*32 + lane == rl) e = 0.0f;
                rs += e;
                csum[cs] += e;
            }
            #pragma unroll
            for (int o = 16; o; o >>= 1) rs += __shfl_xor_sync(0xffffffffu, rs, o);
            if (lane == 0) g_pneg[b][a*SB + rloc] = rs;
        }

        if (!diag){
            #pragma unroll
            for (int cs = 0; cs < 8; cs++) csum_sh[w][cs*32 + lane] = csum[cs];
            __syncthreads();
            for (int c = tid; c < SB; c += 256){
                float s = 0.0f;
                #pragma unroll
                for (int ww = 0; ww < 8; ww++) s += csum_sh[ww][c];
                g_pneg[a][b*SB + c] = s;
            }
        }
    }
}

// ---------------- Final reduce ----------------
__global__ __launch_bounds__(256) void reduce_kernel(float* __restrict__ out)
{
    int i = blockIdx.x * 256 + threadIdx.x;
    float sp = g_spos[0][i] + g_spos[1][i];
    float sn = 0.0f;
    #pragma unroll
    for (int k = 0; k < NB; k++) sn += g_pneg[k][i];
    out[i] = TLN2C * (flog2_fast(sn) - flog2_fast(sp));
}

extern "C" void kernel_launch(void* const* d_in, const int* in_sizes, int n_in,
                              void* d_out, int out_size)
{
    const float* pos = (const float*)d_in[0];
    const float* z   = (const float*)d_in[1];
    const float* W1  = (const float*)d_in[2];  const float* b1 = (const float*)d_in[3];
    const float* W2  = (const float*)d_in[4];  const float* b2 = (const float*)d_in[5];
    const float* W3  = (const float*)d_in[6];  const float* b3 = (const float*)d_in[7];
    const float* W4  = (const float*)d_in[8];  const float* b4 = (const float*)d_in[9];
    const float* W5  = (const float*)d_in[10]; const float* b5 = (const float*)d_in[11];
    (void)in_sizes; (void)n_in; (void)out_size;

    mlp_kernel<<<N_PTS / RT, 128>>>(z, W1, b1, W2, b2, W3, b3, W4, b4, W5, b5);
    energy_kernel<<<POS_BLOCKS + NEG_TILES, 256>>>(pos);
    reduce_kernel<<<N_PTS / 256, 256>>>((float*)d_out);
}